// round 1
// baseline (speedup 1.0000x reference)
#include <cuda_runtime.h>

#define NB 4
#define CCH 256
#define HH 64
#define WW 64
#define HWP (HH*WW)

// ---------------- scratch (static device arrays; no allocation) ----------------
__device__ float g_pxb[NB*CCH*HWP];   // 16 MB
__device__ float g_pxc[NB*CCH*HWP];   // 16 MB

__device__ __forceinline__ int refl(int i, int n) {
    if (i < 0) i = -i;
    if (i >= n) i = 2*n - 2 - i;
    return i;
}

// ---------------- Kernel 1: fused 1x1 convs as GEMM ----------------
// out[n, o, p] = sum_c Wsel[o,c] * x[n,c,p] + bias[o], o in [0,512)
// o < 256 -> (Wb, bb) -> g_pxb ; o >= 256 -> (Wc, bc) -> g_pxc
#define BM 64
#define BN 64
#define BK 16

__global__ void __launch_bounds__(256) conv1x1_kernel(
    const float* __restrict__ x,
    const float* __restrict__ Wb, const float* __restrict__ bb,
    const float* __restrict__ Wc, const float* __restrict__ bc)
{
    __shared__ float sW[BK][BM + 1];   // +1 pad: conflict-free transpose store
    __shared__ float sX[BK][BN];

    const int n  = blockIdx.z;
    const int om = blockIdx.y * BM;          // output-channel tile (0..511)
    const int pn = blockIdx.x * BN;          // pixel tile
    const int t  = threadIdx.x;              // 0..255
    const int tx = t & 15;
    const int ty = t >> 4;

    float acc[4][4] = {};

    const float* xn = x + (size_t)n * CCH * HWP + pn;

    for (int kk = 0; kk < CCH; kk += BK) {
        // load W tile (64 o-rows x 16 c-cols), transposed into sW[c][o]
        #pragma unroll
        for (int s = 0; s < 4; s++) {
            int idx = t + s * 256;           // 0..1023
            int o   = idx >> 4;
            int c   = idx & 15;
            int og  = om + o;
            const float* Wsrc = (og < CCH) ? Wb : Wc;
            int orow = (og < CCH) ? og : og - CCH;
            sW[c][o] = Wsrc[orow * CCH + kk + c];
        }
        // load X tile (16 c-rows x 64 pixels)
        #pragma unroll
        for (int s = 0; s < 4; s++) {
            int idx = t + s * 256;
            int c   = idx >> 6;
            int p   = idx & 63;
            sX[c][p] = xn[(size_t)(kk + c) * HWP + p];
        }
        __syncthreads();

        #pragma unroll
        for (int k = 0; k < BK; k++) {
            float a0 = sW[k][ty*4 + 0];
            float a1 = sW[k][ty*4 + 1];
            float a2 = sW[k][ty*4 + 2];
            float a3 = sW[k][ty*4 + 3];
            float4 b = *(const float4*)&sX[k][tx*4];
            acc[0][0] += a0*b.x; acc[0][1] += a0*b.y; acc[0][2] += a0*b.z; acc[0][3] += a0*b.w;
            acc[1][0] += a1*b.x; acc[1][1] += a1*b.y; acc[1][2] += a1*b.z; acc[1][3] += a1*b.w;
            acc[2][0] += a2*b.x; acc[2][1] += a2*b.y; acc[2][2] += a2*b.z; acc[2][3] += a2*b.w;
            acc[3][0] += a3*b.x; acc[3][1] += a3*b.y; acc[3][2] += a3*b.z; acc[3][3] += a3*b.w;
        }
        __syncthreads();
    }

    // epilogue: add bias, store float4
    #pragma unroll
    for (int i = 0; i < 4; i++) {
        int og = om + ty*4 + i;
        float bias;
        float* dst;
        if (og < CCH) {
            bias = bb[og];
            dst  = g_pxb + ((size_t)(n * CCH + og) * HWP) + pn + tx*4;
        } else {
            int oc = og - CCH;
            bias = bc[oc];
            dst  = g_pxc + ((size_t)(n * CCH + oc) * HWP) + pn + tx*4;
        }
        float4 v;
        v.x = acc[i][0] + bias;
        v.y = acc[i][1] + bias;
        v.z = acc[i][2] + bias;
        v.w = acc[i][3] + bias;
        *(float4*)dst = v;
    }
}

// ---------------- Kernel 2: 5x5 neighborhood attention ----------------
#define TS 8          // pixel tile side -> 64 pixels / block
#define HALO 12       // TS + 4
#define CK 32         // channel chunk

__global__ void __launch_bounds__(256) attn_kernel(
    const float* __restrict__ x,
    const float* __restrict__ alpha,
    float* __restrict__ out)
{
    __shared__ float sPb[CK][HALO*HALO];   // 18 KB  pxb halo chunk
    __shared__ float sPc[CK][TS*TS];       //  8 KB  pxc chunk
    __shared__ float sE[TS*TS][26];        // 6.5 KB energy -> attn (25, pad 26)

    const int n  = blockIdx.z;
    const int h0 = blockIdx.y * TS;
    const int w0 = blockIdx.x * TS;
    const int t  = threadIdx.x;            // 0..255
    const int p  = t & 63;                 // local pixel
    const int g  = t >> 6;                 // k-group 0..3
    const int py = p >> 3;
    const int px = p & 7;

    // this thread's neighbor set: k = g, g+4, g+8, ... (<=7 entries)
    int nofs[7];
    int nk = 0;
    #pragma unroll
    for (int k0 = 0; k0 < 25; k0++) {
        if ((k0 & 3) == g) { // k0 % 4 == g
            int di = k0 / 5, dj = k0 % 5;
            nofs[nk++] = (py + di) * HALO + (px + dj);
        }
    }
    #pragma unroll
    for (int j = 0; j < 7; j++) if (j >= nk) nofs[j] = 0;   // pad (acc unused)

    float acc[7] = {0.f,0.f,0.f,0.f,0.f,0.f,0.f};

    const size_t baseB = (size_t)n * CCH * HWP;

    // ---- Phase 1: energy accumulation over channel chunks ----
    for (int cc = 0; cc < CCH; cc += CK) {
        for (int idx = t; idx < CK * HALO * HALO; idx += 256) {
            int c  = idx / (HALO*HALO);
            int r  = idx - c * (HALO*HALO);
            int hy = r / HALO;
            int wx = r - hy * HALO;
            int gh = refl(h0 - 2 + hy, HH);
            int gw = refl(w0 - 2 + wx, WW);
            sPb[c][r] = g_pxb[baseB + (size_t)(cc + c) * HWP + gh * WW + gw];
        }
        for (int idx = t; idx < CK * TS * TS; idx += 256) {
            int c  = idx >> 6;
            int pp = idx & 63;
            int gh = h0 + (pp >> 3);
            int gw = w0 + (pp & 7);
            sPc[c][pp] = g_pxc[baseB + (size_t)(cc + c) * HWP + gh * WW + gw];
        }
        __syncthreads();

        #pragma unroll 4
        for (int c = 0; c < CK; c++) {
            float pc = sPc[c][p];
            #pragma unroll
            for (int j = 0; j < 7; j++)
                acc[j] += pc * sPb[c][nofs[j]];
        }
        __syncthreads();
    }

    // write energies
    for (int j = 0; j < nk; j++) sE[p][g + 4*j] = acc[j];
    __syncthreads();

    // ---- Phase 2: softmax over 25 (one thread per pixel) ----
    if (t < 64) {
        float m = -1e30f;
        #pragma unroll
        for (int k = 0; k < 25; k++) m = fmaxf(m, sE[t][k]);
        float s = 0.f;
        #pragma unroll
        for (int k = 0; k < 25; k++) {
            float v = __expf(sE[t][k] - m);
            sE[t][k] = v;
            s += v;
        }
        float inv = 1.f / s;
        #pragma unroll
        for (int k = 0; k < 25; k++) sE[t][k] *= inv;
    }
    __syncthreads();

    // attn weights into registers (per-thread pixel p)
    float attn[25];
    #pragma unroll
    for (int k = 0; k < 25; k++) attn[k] = sE[p][k];
    const float alphav = alpha[0];

    // ---- Phase 3: fusion + residual ----
    for (int cc = 0; cc < CCH; cc += CK) {
        __syncthreads();   // guard: previous chunk's sPb reads done before overwrite
        for (int idx = t; idx < CK * HALO * HALO; idx += 256) {
            int c  = idx / (HALO*HALO);
            int r  = idx - c * (HALO*HALO);
            int hy = r / HALO;
            int wx = r - hy * HALO;
            int gh = refl(h0 - 2 + hy, HH);
            int gw = refl(w0 - 2 + wx, WW);
            sPb[c][r] = g_pxb[baseB + (size_t)(cc + c) * HWP + gh * WW + gw];
        }
        __syncthreads();

        #pragma unroll
        for (int m = 0; m < CK/4; m++) {
            int cl = g * (CK/4) + m;   // each k-group covers 8 channels
            float f = 0.f;
            #pragma unroll
            for (int k = 0; k < 25; k++) {
                int di = k / 5, dj = k % 5;
                f += attn[k] * sPb[cl][(py + di) * HALO + (px + dj)];
            }
            size_t gi = baseB + (size_t)(cc + cl) * HWP + (h0 + py) * WW + (w0 + px);
            out[gi] = alphav * f + x[gi];
        }
    }
}

extern "C" void kernel_launch(void* const* d_in, const int* in_sizes, int n_in,
                              void* d_out, int out_size)
{
    const float* x     = (const float*)d_in[0];
    const float* Wb    = (const float*)d_in[1];
    const float* bb    = (const float*)d_in[2];
    const float* Wc    = (const float*)d_in[3];
    const float* bc    = (const float*)d_in[4];
    const float* alpha = (const float*)d_in[5];
    float* out = (float*)d_out;

    dim3 g1(HWP / BN, (2 * CCH) / BM, NB);   // 64 x 8 x 4
    conv1x1_kernel<<<g1, 256>>>(x, Wb, bb, Wc, bc);

    dim3 g2(WW / TS, HH / TS, NB);           // 8 x 8 x 4
    attn_kernel<<<g2, 256>>>(x, alpha, out);
}